// round 1
// baseline (speedup 1.0000x reference)
#include <cuda_runtime.h>
#include <cuda_bf16.h>
#include <cstdint>

static constexpr int Bn = 128;
static constexpr int Sn = 1024;
static constexpr int Dn = 1024;
static constexpr float LOG2F_ = 0.69314718055994530942f;

__device__ double g_pos_acc;
__device__ double g_neg_acc;
__device__ int g_lens[Bn];
__device__ __nv_bfloat16 g_ctx_bf16[Bn * Dn];

// ---------------------------------------------------------------------------
// prep: ctx fp32 -> bf16, lens[b] = max(1, sum(mask[b,:])), zero accumulators
// ---------------------------------------------------------------------------
__global__ void prep_kernel(const float* __restrict__ ctx, const int* __restrict__ mask) {
    const int b = blockIdx.x;
    const int tid = threadIdx.x;
    for (int i = tid; i < Dn; i += 256)
        g_ctx_bf16[b * Dn + i] = __float2bfloat16(ctx[b * Dn + i]);
    int s = 0;
    for (int i = tid; i < Sn; i += 256) s += mask[b * Sn + i];
    __shared__ int red[256];
    red[tid] = s;
    __syncthreads();
    for (int off = 128; off > 0; off >>= 1) {
        if (tid < off) red[tid] += red[tid + off];
        __syncthreads();
    }
    if (tid == 0) {
        g_lens[b] = red[0] > 0 ? red[0] : 1;
        if (b == 0) { g_pos_acc = 0.0; g_neg_acc = 0.0; }
    }
}

__device__ __forceinline__ void ldm_x4(uint32_t& r0, uint32_t& r1, uint32_t& r2,
                                       uint32_t& r3, uint32_t addr) {
    asm volatile("ldmatrix.sync.aligned.m8n8.x4.shared.b16 {%0,%1,%2,%3}, [%4];"
                 : "=r"(r0), "=r"(r1), "=r"(r2), "=r"(r3) : "r"(addr));
}

__device__ __forceinline__ void mma_bf16(float* c, const uint32_t* a, const uint32_t* b) {
    asm volatile("mma.sync.aligned.m16n8k16.row.col.f32.bf16.bf16.f32 "
                 "{%0,%1,%2,%3}, {%4,%5,%6,%7}, {%8,%9}, {%0,%1,%2,%3};"
                 : "+f"(c[0]), "+f"(c[1]), "+f"(c[2]), "+f"(c[3])
                 : "r"(a[0]), "r"(a[1]), "r"(a[2]), "r"(a[3]), "r"(b[0]), "r"(b[1]));
}

// ---------------------------------------------------------------------------
// main: per block, M-tile of 128 tokens (single b), N = all 128 graphs.
// K loop BK=64, fp32->bf16 in-register, swizzled smem, mma.sync bf16,
// fused softplus epilogue + reduction.
// ---------------------------------------------------------------------------
__global__ void __launch_bounds__(256, 1)
mi_main_kernel(const float* __restrict__ seq) {
    __shared__ __align__(16) uint8_t smA[128 * 128];
    __shared__ __align__(16) uint8_t smB[128 * 128];
    __shared__ float redp[8], redn[8];

    const int tid = threadIdx.x;
    const int lane = tid & 31;
    const int w = tid >> 5;
    const int wm = w & 3;      // warp row: 4 x 32 rows
    const int wn = w >> 2;     // warp col: 2 x 64 cols
    const int tok0 = blockIdx.x * 128;
    const int b = tok0 >> 10;          // 128 tokens never straddle a batch row
    const int s0 = tok0 & (Sn - 1);

    float acc[2][8][4];
    #pragma unroll
    for (int i = 0; i < 2; i++)
        #pragma unroll
        for (int j = 0; j < 8; j++)
            #pragma unroll
            for (int r = 0; r < 4; r++) acc[i][j][r] = 0.0f;

    float4 pa[8];   // prefetch regs: A chunk (128x64 fp32 slice, per-thread share)
    uint4  pb[4];   // prefetch regs: B chunk (128x64 bf16)

    auto load_pf = [&](int kb) {
        #pragma unroll
        for (int j = 0; j < 8; j++) {
            int fi = tid + j * 256;       // 2048 float4 per chunk
            int rw = fi >> 4;
            int fc = fi & 15;
            pa[j] = *reinterpret_cast<const float4*>(
                seq + (size_t)(tok0 + rw) * Dn + kb * 64 + fc * 4);
        }
        #pragma unroll
        for (int j = 0; j < 4; j++) {
            int lc = tid + j * 256;       // 1024 16B chunks
            int rw = lc >> 3;
            int cc = lc & 7;
            pb[j] = *reinterpret_cast<const uint4*>(
                g_ctx_bf16 + rw * Dn + kb * 64 + cc * 8);
        }
    };

    auto store_pf = [&]() {
        #pragma unroll
        for (int j = 0; j < 8; j++) {
            int fi = tid + j * 256;
            int rw = fi >> 4;
            int fc = fi & 15;
            __nv_bfloat162 h0 = __float22bfloat162_rn(make_float2(pa[j].x, pa[j].y));
            __nv_bfloat162 h1 = __float22bfloat162_rn(make_float2(pa[j].z, pa[j].w));
            uint2 v;
            v.x = *reinterpret_cast<uint32_t*>(&h0);
            v.y = *reinterpret_cast<uint32_t*>(&h1);
            int phys = (fc >> 1) ^ (rw & 7);       // 16B-chunk XOR swizzle
            *reinterpret_cast<uint2*>(smA + rw * 128 + phys * 16 + (fc & 1) * 8) = v;
        }
        #pragma unroll
        for (int j = 0; j < 4; j++) {
            int lc = tid + j * 256;
            int rw = lc >> 3;
            int cc = lc & 7;
            *reinterpret_cast<uint4*>(smB + rw * 128 + ((cc ^ (rw & 7)) * 16)) = pb[j];
        }
    };

    const uint32_t sAb = (uint32_t)__cvta_generic_to_shared(smA);
    const uint32_t sBb = (uint32_t)__cvta_generic_to_shared(smB);

    load_pf(0);
    for (int kb = 0; kb < 16; kb++) {
        store_pf();
        __syncthreads();
        if (kb < 15) load_pf(kb + 1);   // overlap next-chunk LDG with compute
        #pragma unroll
        for (int ks = 0; ks < 4; ks++) {
            uint32_t afr[2][4];
            #pragma unroll
            for (int mf = 0; mf < 2; mf++) {
                int r = wm * 32 + mf * 16 + (lane & 15);
                int ch = ks * 2 + (lane >> 4);
                ldm_x4(afr[mf][0], afr[mf][1], afr[mf][2], afr[mf][3],
                       sAb + r * 128 + ((ch ^ (r & 7)) << 4));
            }
            uint32_t bfr[8][2];
            #pragma unroll
            for (int nq = 0; nq < 4; nq++) {
                int r = wn * 64 + nq * 16 + (lane & 7) + ((lane & 16) >> 1);
                int ch = ks * 2 + ((lane >> 3) & 1);
                uint32_t t0, t1, t2, t3;
                ldm_x4(t0, t1, t2, t3, sBb + r * 128 + ((ch ^ (r & 7)) << 4));
                bfr[nq * 2][0] = t0; bfr[nq * 2][1] = t1;
                bfr[nq * 2 + 1][0] = t2; bfr[nq * 2 + 1][1] = t3;
            }
            #pragma unroll
            for (int mf = 0; mf < 2; mf++)
                #pragma unroll
                for (int nf = 0; nf < 8; nf++)
                    mma_bf16(acc[mf][nf], afr[mf], bfr[nf]);
        }
        __syncthreads();
    }

    // Epilogue: JSD terms, masked by (s < lens[b]) and diag/off-diag split
    const int len = g_lens[b];
    float pos = 0.0f, neg = 0.0f;
    #pragma unroll
    for (int mf = 0; mf < 2; mf++) {
        #pragma unroll
        for (int nf = 0; nf < 8; nf++) {
            #pragma unroll
            for (int r = 0; r < 4; r++) {
                int row = wm * 32 + mf * 16 + (lane >> 2) + ((r & 2) ? 8 : 0);
                int s   = s0 + row;
                int k   = wn * 64 + nf * 8 + ((lane & 3) << 1) + (r & 1);
                float v = acc[mf][nf][r];
                if (s < len) {
                    float sp = fmaxf(-v, 0.0f) + __logf(1.0f + __expf(-fabsf(v)));
                    if (k == b) pos += LOG2F_ - sp;
                    else        neg += sp + v - LOG2F_;
                }
            }
        }
    }
    #pragma unroll
    for (int off = 16; off > 0; off >>= 1) {
        pos += __shfl_xor_sync(0xffffffffu, pos, off);
        neg += __shfl_xor_sync(0xffffffffu, neg, off);
    }
    if (lane == 0) { redp[w] = pos; redn[w] = neg; }
    __syncthreads();
    if (tid == 0) {
        double p = 0.0, n = 0.0;
        #pragma unroll
        for (int i = 0; i < 8; i++) { p += (double)redp[i]; n += (double)redn[i]; }
        atomicAdd(&g_pos_acc, p);
        atomicAdd(&g_neg_acc, n);
    }
}

// ---------------------------------------------------------------------------
// finalize: num_nodes = sum(lens); out = E_neg - E_pos
// ---------------------------------------------------------------------------
__global__ void finalize_kernel(float* __restrict__ out) {
    __shared__ int red[Bn];
    const int t = threadIdx.x;
    red[t] = g_lens[t];
    __syncthreads();
    for (int off = 64; off > 0; off >>= 1) {
        if (t < off) red[t] += red[t + off];
        __syncthreads();
    }
    if (t == 0) {
        double nn = (double)red[0];
        out[0] = (float)(g_neg_acc / (nn * (double)(Bn - 1)) - g_pos_acc / nn);
    }
}

extern "C" void kernel_launch(void* const* d_in, const int* in_sizes, int n_in,
                              void* d_out, int out_size) {
    const float* seq  = (const float*)d_in[0];
    const float* ctx  = (const float*)d_in[1];
    const int*   mask = (const int*)d_in[2];
    prep_kernel<<<Bn, 256>>>(ctx, mask);
    mi_main_kernel<<<(Bn * Sn) / 128, 256>>>(seq);
    finalize_kernel<<<1, Bn>>>((float*)d_out);
}

// round 3
// speedup vs baseline: 1.0117x; 1.0117x over previous
#include <cuda_runtime.h>
#include <cuda_bf16.h>
#include <cstdint>

static constexpr int Bn = 128;
static constexpr int Sn = 1024;
static constexpr int Dn = 1024;
static constexpr float LOG2F_ = 0.69314718055994530942f;

__device__ double g_pos_acc;
__device__ double g_neg_acc;
__device__ int g_lens[Bn];
__device__ __nv_bfloat16 g_ctx_bf16[Bn * Dn];

// smem layout (dynamic, 64 KB): A0 | A1 | B0 | B1, each 128x64 bf16 = 16 KB
__host__ __device__ constexpr uint32_t OFF_A(int buf) { return buf ? 16384u : 0u; }
__host__ __device__ constexpr uint32_t OFF_B(int buf) { return buf ? 49152u : 32768u; }

// ---------------------------------------------------------------------------
// prep: grid=128, block=256. Row b: convert 1024 ctx floats (1 float4/thread),
// sum 1024 mask ints (1 int4/thread, warp shfl reduce). Zero accumulators.
// ---------------------------------------------------------------------------
__global__ void __launch_bounds__(256) prep_kernel(const float* __restrict__ ctx,
                                                   const int* __restrict__ mask) {
    const int b = blockIdx.x;
    const int tid = threadIdx.x;
    // ctx row conversion: 256 float4 per row
    float4 v = reinterpret_cast<const float4*>(ctx + b * Dn)[tid];
    __nv_bfloat162 h0 = __float22bfloat162_rn(make_float2(v.x, v.y));
    __nv_bfloat162 h1 = __float22bfloat162_rn(make_float2(v.z, v.w));
    uint2 packed;
    packed.x = *reinterpret_cast<uint32_t*>(&h0);
    packed.y = *reinterpret_cast<uint32_t*>(&h1);
    reinterpret_cast<uint2*>(g_ctx_bf16 + b * Dn)[tid] = packed;
    // mask row sum: 256 int4 per row
    int4 m = reinterpret_cast<const int4*>(mask + b * Sn)[tid];
    int s = m.x + m.y + m.z + m.w;
    #pragma unroll
    for (int off = 16; off > 0; off >>= 1)
        s += __shfl_xor_sync(0xffffffffu, s, off);
    __shared__ int wsum[8];
    if ((tid & 31) == 0) wsum[tid >> 5] = s;
    __syncthreads();
    if (tid == 0) {
        int tot = 0;
        #pragma unroll
        for (int i = 0; i < 8; i++) tot += wsum[i];
        g_lens[b] = tot > 0 ? tot : 1;
        if (b == 0) { g_pos_acc = 0.0; g_neg_acc = 0.0; }
    }
}

__device__ __forceinline__ void ldm_x4(uint32_t& r0, uint32_t& r1, uint32_t& r2,
                                       uint32_t& r3, uint32_t addr) {
    asm volatile("ldmatrix.sync.aligned.m8n8.x4.shared.b16 {%0,%1,%2,%3}, [%4];"
                 : "=r"(r0), "=r"(r1), "=r"(r2), "=r"(r3) : "r"(addr));
}

__device__ __forceinline__ void mma_bf16(float* c, const uint32_t* a, const uint32_t* b) {
    asm volatile("mma.sync.aligned.m16n8k16.row.col.f32.bf16.bf16.f32 "
                 "{%0,%1,%2,%3}, {%4,%5,%6,%7}, {%8,%9}, {%0,%1,%2,%3};"
                 : "+f"(c[0]), "+f"(c[1]), "+f"(c[2]), "+f"(c[3])
                 : "r"(a[0]), "r"(a[1]), "r"(a[2]), "r"(a[3]), "r"(b[0]), "r"(b[1]));
}

#define CP_ASYNC16(dst, src) \
    asm volatile("cp.async.cg.shared.global [%0], [%1], 16;" :: "r"(dst), "l"(src))
#define CP_COMMIT() asm volatile("cp.async.commit_group;")
#define CP_WAIT0()  asm volatile("cp.async.wait_group 0;")

// ---------------------------------------------------------------------------
// main: M-tile=128 tokens (single b), N=128 graphs, BK=64, double-buffered.
// B via cp.async (bf16 staged by prep); A via LDG fp32 -> cvt -> STS into the
// alternate buffer. One __syncthreads per K-chunk.
// ---------------------------------------------------------------------------
__global__ void __launch_bounds__(256, 1)
mi_main_kernel(const float* __restrict__ seq) {
    extern __shared__ __align__(16) uint8_t dynsm[];
    __shared__ float redp[8], redn[8];

    const int tid = threadIdx.x;
    const int lane = tid & 31;
    const int w = tid >> 5;
    const int wm = w & 3;          // 4 warp-rows x 32 rows
    const int wn = w >> 2;         // 2 warp-cols x 64 cols
    const int tok0 = blockIdx.x * 128;
    const int b = tok0 >> 10;
    const int s0 = tok0 & (Sn - 1);

    const uint32_t sBase = (uint32_t)__cvta_generic_to_shared(dynsm);

    float acc[2][8][4];
    #pragma unroll
    for (int i = 0; i < 2; i++)
        #pragma unroll
        for (int j = 0; j < 8; j++)
            #pragma unroll
            for (int r = 0; r < 4; r++) acc[i][j][r] = 0.0f;

    float4 pa[8];  // A prefetch regs: 128x64 fp32 chunk, 8 float4/thread

    auto loadA = [&](int kb) {
        #pragma unroll
        for (int j = 0; j < 8; j++) {
            int fi = tid + j * 256;          // 2048 float4 per chunk
            int rw = fi >> 4;
            int fc = fi & 15;
            pa[j] = *reinterpret_cast<const float4*>(
                seq + (size_t)(tok0 + rw) * Dn + kb * 64 + fc * 4);
        }
    };
    auto storeA = [&](int buf) {
        #pragma unroll
        for (int j = 0; j < 8; j++) {
            int fi = tid + j * 256;
            int rw = fi >> 4;
            int fc = fi & 15;
            __nv_bfloat162 h0 = __float22bfloat162_rn(make_float2(pa[j].x, pa[j].y));
            __nv_bfloat162 h1 = __float22bfloat162_rn(make_float2(pa[j].z, pa[j].w));
            uint2 vv;
            vv.x = *reinterpret_cast<uint32_t*>(&h0);
            vv.y = *reinterpret_cast<uint32_t*>(&h1);
            int phys = (fc >> 1) ^ (rw & 7);
            *reinterpret_cast<uint2*>(dynsm + OFF_A(buf) + rw * 128 + phys * 16 +
                                      (fc & 1) * 8) = vv;
        }
    };
    auto loadB = [&](int kb, int buf) {
        #pragma unroll
        for (int j = 0; j < 4; j++) {
            int lc = tid + j * 256;          // 1024 16B chunks
            int rw = lc >> 3;
            int cc = lc & 7;
            uint32_t dst = sBase + OFF_B(buf) + rw * 128 + ((cc ^ (rw & 7)) << 4);
            CP_ASYNC16(dst, g_ctx_bf16 + rw * Dn + kb * 64 + cc * 8);
        }
    };
    auto compute = [&](int buf) {
        const uint32_t aB = sBase + OFF_A(buf);
        const uint32_t bB = sBase + OFF_B(buf);
        #pragma unroll
        for (int ks = 0; ks < 4; ks++) {
            uint32_t afr[2][4];
            #pragma unroll
            for (int mf = 0; mf < 2; mf++) {
                int r = wm * 32 + mf * 16 + (lane & 15);
                int ch = ks * 2 + (lane >> 4);
                ldm_x4(afr[mf][0], afr[mf][1], afr[mf][2], afr[mf][3],
                       aB + r * 128 + ((ch ^ (r & 7)) << 4));
            }
            uint32_t bfr[8][2];
            #pragma unroll
            for (int nq = 0; nq < 4; nq++) {
                int r = wn * 64 + nq * 16 + (lane & 7) + ((lane & 16) >> 1);
                int ch = ks * 2 + ((lane >> 3) & 1);
                uint32_t t0, t1, t2, t3;
                ldm_x4(t0, t1, t2, t3, bB + r * 128 + ((ch ^ (r & 7)) << 4));
                bfr[nq * 2][0] = t0; bfr[nq * 2][1] = t1;
                bfr[nq * 2 + 1][0] = t2; bfr[nq * 2 + 1][1] = t3;
            }
            #pragma unroll
            for (int mf = 0; mf < 2; mf++)
                #pragma unroll
                for (int nf = 0; nf < 8; nf++)
                    mma_bf16(acc[mf][nf], afr[mf], bfr[nf]);
        }
    };

    // startup: fill buffer 0, prefetch A(1) regs
    loadA(0);
    loadB(0, 0);
    CP_COMMIT();
    storeA(0);
    loadA(1);
    CP_WAIT0();
    __syncthreads();

    #pragma unroll 2
    for (int kb = 0; kb < 16; kb++) {
        const int cur = kb & 1;
        const int nxt = cur ^ 1;
        if (kb < 15) {
            loadB(kb + 1, nxt);
            CP_COMMIT();
            storeA(nxt);               // regs for kb+1 already resident
        }
        if (kb < 14) loadA(kb + 2);    // deep LDG prefetch over compute
        compute(cur);
        if (kb < 15) {
            CP_WAIT0();
            __syncthreads();
        }
    }

    // Epilogue: JSD terms, masked by (s < lens[b]) and diag/off-diag split
    const int len = g_lens[b];
    float pos = 0.0f, neg = 0.0f;
    #pragma unroll
    for (int mf = 0; mf < 2; mf++) {
        #pragma unroll
        for (int nf = 0; nf < 8; nf++) {
            #pragma unroll
            for (int r = 0; r < 4; r++) {
                int row = wm * 32 + mf * 16 + (lane >> 2) + ((r & 2) ? 8 : 0);
                int s   = s0 + row;
                int k   = wn * 64 + nf * 8 + ((lane & 3) << 1) + (r & 1);
                float v = acc[mf][nf][r];
                if (s < len) {
                    float sp = fmaxf(-v, 0.0f) + __logf(1.0f + __expf(-fabsf(v)));
                    if (k == b) pos += LOG2F_ - sp;
                    else        neg += sp + v - LOG2F_;
                }
            }
        }
    }
    #pragma unroll
    for (int off = 16; off > 0; off >>= 1) {
        pos += __shfl_xor_sync(0xffffffffu, pos, off);
        neg += __shfl_xor_sync(0xffffffffu, neg, off);
    }
    if (lane == 0) { redp[w] = pos; redn[w] = neg; }
    __syncthreads();
    if (tid == 0) {
        double p = 0.0, n = 0.0;
        #pragma unroll
        for (int i = 0; i < 8; i++) { p += (double)redp[i]; n += (double)redn[i]; }
        atomicAdd(&g_pos_acc, p);
        atomicAdd(&g_neg_acc, n);
    }
}

// ---------------------------------------------------------------------------
// finalize: num_nodes = sum(lens); out = E_neg - E_pos
// ---------------------------------------------------------------------------
__global__ void finalize_kernel(float* __restrict__ out) {
    __shared__ int red[Bn];
    const int t = threadIdx.x;
    red[t] = g_lens[t];
    __syncthreads();
    for (int off = 64; off > 0; off >>= 1) {
        if (t < off) red[t] += red[t + off];
        __syncthreads();
    }
    if (t == 0) {
        double nn = (double)red[0];
        out[0] = (float)(g_neg_acc / (nn * (double)(Bn - 1)) - g_pos_acc / nn);
    }
}

extern "C" void kernel_launch(void* const* d_in, const int* in_sizes, int n_in,
                              void* d_out, int out_size) {
    const float* seq  = (const float*)d_in[0];
    const float* ctx  = (const float*)d_in[1];
    const int*   mask = (const int*)d_in[2];
    static bool attr_set = false;
    if (!attr_set) {
        cudaFuncSetAttribute(mi_main_kernel,
                             cudaFuncAttributeMaxDynamicSharedMemorySize, 65536);
        attr_set = true;
    }
    prep_kernel<<<Bn, 256>>>(ctx, mask);
    mi_main_kernel<<<(Bn * Sn) / 128, 256, 65536>>>(seq);
    finalize_kernel<<<1, Bn>>>((float*)d_out);
}

// round 5
// speedup vs baseline: 1.0262x; 1.0144x over previous
#include <cuda_runtime.h>
#include <cuda_bf16.h>
#include <cstdint>

static constexpr int Bn = 128;
static constexpr int Sn = 1024;
static constexpr int Dn = 1024;
static constexpr float LOG2F_ = 0.69314718055994530942f;

__device__ double g_pos_acc;
__device__ double g_neg_acc;
__device__ int g_lens[Bn];
__device__ int g_ticket;
__device__ __nv_bfloat16 g_ctx_bf16[Bn * Dn];

// dynamic smem (1024-aligned window): A0 | A1 | B0 | B1, each 128x128B = 16 KB
__host__ __device__ constexpr uint32_t OFF_A(int buf) { return buf ? 16384u : 0u; }
__host__ __device__ constexpr uint32_t OFF_B(int buf) { return buf ? 49152u : 32768u; }

// ---------------------------------------------------------------------------
// prep: ctx fp32 -> bf16 (1 float4/thread), lens via int4 + shfl reduction,
// zero global accumulators + ticket (graph-replay safe).
// ---------------------------------------------------------------------------
__global__ void __launch_bounds__(256) prep_kernel(const float* __restrict__ ctx,
                                                   const int* __restrict__ mask) {
    const int b = blockIdx.x;
    const int tid = threadIdx.x;
    float4 v = reinterpret_cast<const float4*>(ctx + b * Dn)[tid];
    __nv_bfloat162 h0 = __float22bfloat162_rn(make_float2(v.x, v.y));
    __nv_bfloat162 h1 = __float22bfloat162_rn(make_float2(v.z, v.w));
    uint2 packed;
    packed.x = *reinterpret_cast<uint32_t*>(&h0);
    packed.y = *reinterpret_cast<uint32_t*>(&h1);
    reinterpret_cast<uint2*>(g_ctx_bf16 + b * Dn)[tid] = packed;
    int4 m = reinterpret_cast<const int4*>(mask + b * Sn)[tid];
    int s = m.x + m.y + m.z + m.w;
    #pragma unroll
    for (int off = 16; off > 0; off >>= 1)
        s += __shfl_xor_sync(0xffffffffu, s, off);
    __shared__ int wsum[8];
    if ((tid & 31) == 0) wsum[tid >> 5] = s;
    __syncthreads();
    if (tid == 0) {
        int tot = 0;
        #pragma unroll
        for (int i = 0; i < 8; i++) tot += wsum[i];
        g_lens[b] = tot > 0 ? tot : 1;
        if (b == 0) { g_pos_acc = 0.0; g_neg_acc = 0.0; g_ticket = 0; }
    }
}

__device__ __forceinline__ void ldm_x4(uint32_t& r0, uint32_t& r1, uint32_t& r2,
                                       uint32_t& r3, uint32_t addr) {
    asm volatile("ldmatrix.sync.aligned.m8n8.x4.shared.b16 {%0,%1,%2,%3}, [%4];"
                 : "=r"(r0), "=r"(r1), "=r"(r2), "=r"(r3) : "r"(addr));
}

__device__ __forceinline__ void mma_bf16(float* c, const uint32_t* a, const uint32_t* b) {
    asm volatile("mma.sync.aligned.m16n8k16.row.col.f32.bf16.bf16.f32 "
                 "{%0,%1,%2,%3}, {%4,%5,%6,%7}, {%8,%9}, {%0,%1,%2,%3};"
                 : "+f"(c[0]), "+f"(c[1]), "+f"(c[2]), "+f"(c[3])
                 : "r"(a[0]), "r"(a[1]), "r"(a[2]), "r"(a[3]), "r"(b[0]), "r"(b[1]));
}

#define CP_ASYNC16(dst, src) \
    asm volatile("cp.async.cg.shared.global [%0], [%1], 16;" :: "r"(dst), "l"(src))
#define CP_COMMIT() asm volatile("cp.async.commit_group;")
#define CP_WAIT0()  asm volatile("cp.async.wait_group 0;")

// ---------------------------------------------------------------------------
// main: 128 threads / 4 warps, warp grid 2x2, warp tile 64x64 (square -> min
// ldmatrix traffic). 2 CTAs/SM for cross-CTA latency hiding. BM=128 (one b),
// BN=128, BK=64, double-buffered smem. Fused JSD epilogue + final reduction.
// ---------------------------------------------------------------------------
__global__ void __launch_bounds__(128, 2)
mi_main_kernel(const float* __restrict__ seq, float* __restrict__ out) {
    extern __shared__ __align__(16) uint8_t dynsm_raw[];
    __shared__ float redp[4], redn[4];

    const int tid = threadIdx.x;
    const int lane = tid & 31;
    const int w = tid >> 5;        // 0..3
    const int wm = w >> 1;         // warp row (2 x 64 rows)
    const int wn = w & 1;          // warp col (2 x 64 cols)
    const int tok0 = blockIdx.x * 128;
    const int b = tok0 >> 10;
    const int s0 = tok0 & (Sn - 1);

    const uint32_t rawB = (uint32_t)__cvta_generic_to_shared(dynsm_raw);
    const uint32_t sBase = (rawB + 1023u) & ~1023u;
    uint8_t* dynsm = dynsm_raw + (sBase - rawB);

    float acc[4][8][4];
    #pragma unroll
    for (int i = 0; i < 4; i++)
        #pragma unroll
        for (int j = 0; j < 8; j++)
            #pragma unroll
            for (int r = 0; r < 4; r++) acc[i][j][r] = 0.0f;

    float4 pa[8];   // half-chunk A staging: 1024 float4 / 128 threads

    auto loadA_half = [&](int kb, int h) {
        #pragma unroll
        for (int j = 0; j < 8; j++) {
            int fi = tid + j * 128;
            int rw = h * 64 + (fi >> 4);
            int fc = fi & 15;
            pa[j] = *reinterpret_cast<const float4*>(
                seq + (size_t)(tok0 + rw) * Dn + kb * 64 + fc * 4);
        }
    };
    auto storeA_half = [&](int buf, int h) {
        #pragma unroll
        for (int j = 0; j < 8; j++) {
            int fi = tid + j * 128;
            int rw = h * 64 + (fi >> 4);
            int fc = fi & 15;
            __nv_bfloat162 h0 = __float22bfloat162_rn(make_float2(pa[j].x, pa[j].y));
            __nv_bfloat162 h1 = __float22bfloat162_rn(make_float2(pa[j].z, pa[j].w));
            uint2 vv;
            vv.x = *reinterpret_cast<uint32_t*>(&h0);
            vv.y = *reinterpret_cast<uint32_t*>(&h1);
            uint32_t off = rw * 128 + fc * 8;
            uint32_t sw = off ^ ((off >> 3) & 0x70);
            *reinterpret_cast<uint2*>(dynsm + OFF_A(buf) + sw) = vv;
        }
    };
    auto loadB = [&](int kb, int buf) {
        #pragma unroll
        for (int j = 0; j < 8; j++) {
            int lc = tid + j * 128;
            int rw = lc >> 3;
            int cc = lc & 7;
            uint32_t off = rw * 128 + cc * 16;
            uint32_t sw = off ^ ((off >> 3) & 0x70);
            CP_ASYNC16(sBase + OFF_B(buf) + sw, g_ctx_bf16 + rw * Dn + kb * 64 + cc * 8);
        }
    };
    auto compute_ks = [&](int buf, int ks) {
        const uint32_t aB = sBase + OFF_A(buf);
        const uint32_t bB = sBase + OFF_B(buf);
        uint32_t afr[4][4];
        #pragma unroll
        for (int mf = 0; mf < 4; mf++) {
            int r = wm * 64 + mf * 16 + (lane & 15);
            int ch = ks * 2 + (lane >> 4);
            ldm_x4(afr[mf][0], afr[mf][1], afr[mf][2], afr[mf][3],
                   aB + r * 128 + ((ch ^ (r & 7)) << 4));
        }
        uint32_t bfr[8][2];
        #pragma unroll
        for (int nq = 0; nq < 4; nq++) {
            int r = wn * 64 + nq * 16 + (lane & 7) + ((lane & 16) >> 1);
            int ch = ks * 2 + ((lane >> 3) & 1);
            uint32_t t0, t1, t2, t3;
            ldm_x4(t0, t1, t2, t3, bB + r * 128 + ((ch ^ (r & 7)) << 4));
            bfr[nq * 2][0] = t0; bfr[nq * 2][1] = t1;
            bfr[nq * 2 + 1][0] = t2; bfr[nq * 2 + 1][1] = t3;
        }
        #pragma unroll
        for (int mf = 0; mf < 4; mf++)
            #pragma unroll
            for (int nf = 0; nf < 8; nf++)
                mma_bf16(acc[mf][nf], afr[mf], bfr[nf]);
    };

    // prologue: fill buffer 0
    loadA_half(0, 0); storeA_half(0, 0);
    loadA_half(0, 1); storeA_half(0, 1);
    loadB(0, 0); CP_COMMIT();
    CP_WAIT0();
    __syncthreads();

    for (int kb = 0; kb < 16; kb++) {
        const int cur = kb & 1;
        const int nxt = cur ^ 1;
        if (kb < 15) {
            loadB(kb + 1, nxt);
            CP_COMMIT();
            loadA_half(kb + 1, 0);
        }
        compute_ks(cur, 0);
        compute_ks(cur, 1);
        if (kb < 15) {
            storeA_half(nxt, 0);
            loadA_half(kb + 1, 1);
        }
        compute_ks(cur, 2);
        compute_ks(cur, 3);
        if (kb < 15) {
            storeA_half(nxt, 1);
            CP_WAIT0();
        }
        __syncthreads();
    }

    // Epilogue: JSD terms, masked by (s < lens[b]) and diag/off-diag split
    const int len = g_lens[b];
    float pos = 0.0f, neg = 0.0f;
    #pragma unroll
    for (int mf = 0; mf < 4; mf++) {
        #pragma unroll
        for (int nf = 0; nf < 8; nf++) {
            #pragma unroll
            for (int r = 0; r < 4; r++) {
                int row = wm * 64 + mf * 16 + (lane >> 2) + ((r & 2) ? 8 : 0);
                int s   = s0 + row;
                int k   = wn * 64 + nf * 8 + ((lane & 3) << 1) + (r & 1);
                float v = acc[mf][nf][r];
                if (s < len) {
                    float sp = fmaxf(-v, 0.0f) + __logf(1.0f + __expf(-fabsf(v)));
                    if (k == b) pos += LOG2F_ - sp;
                    else        neg += sp + v - LOG2F_;
                }
            }
        }
    }
    #pragma unroll
    for (int off = 16; off > 0; off >>= 1) {
        pos += __shfl_xor_sync(0xffffffffu, pos, off);
        neg += __shfl_xor_sync(0xffffffffu, neg, off);
    }
    if (lane == 0) { redp[w] = pos; redn[w] = neg; }
    __syncthreads();
    if (tid == 0) {
        double p = (double)redp[0] + redp[1] + redp[2] + redp[3];
        double n = (double)redn[0] + redn[1] + redn[2] + redn[3];
        atomicAdd(&g_pos_acc, p);
        atomicAdd(&g_neg_acc, n);
        __threadfence();
        int old = atomicAdd(&g_ticket, 1);
        if (old == (int)gridDim.x - 1) {   // last CTA finalizes
            double nn = 0.0;
            for (int i = 0; i < Bn; i++) nn += (double)g_lens[i];
            double pp = atomicAdd(&g_pos_acc, 0.0);
            double qq = atomicAdd(&g_neg_acc, 0.0);
            out[0] = (float)(qq / (nn * (double)(Bn - 1)) - pp / nn);
        }
    }
}

extern "C" void kernel_launch(void* const* d_in, const int* in_sizes, int n_in,
                              void* d_out, int out_size) {
    const float* seq  = (const float*)d_in[0];
    const float* ctx  = (const float*)d_in[1];
    const int*   mask = (const int*)d_in[2];
    static bool attr_set = false;
    if (!attr_set) {
        cudaFuncSetAttribute(mi_main_kernel,
                             cudaFuncAttributeMaxDynamicSharedMemorySize, 66560);
        attr_set = true;
    }
    prep_kernel<<<Bn, 256>>>(ctx, mask);
    mi_main_kernel<<<(Bn * Sn) / 128, 128, 66560>>>(seq, (float*)d_out);
}